// round 6
// baseline (speedup 1.0000x reference)
#include <cuda_runtime.h>
#include <cuda_fp16.h>

#define B_  32
#define NJ  2048
#define IL  32
#define CC  32
#define LL  32
#define KK  1024  // CC*LL

// Scratch (allocation-free rule: __device__ globals)
__device__ __half2 g_uh[(size_t)B_ * NJ * KK / 2];  // 128 MiB, [b][j][k]
__device__ float   g_b[(size_t)B_ * NJ * CC];       // routing logits
__device__ float   g_s[B_ * KK];                    // s accumulator
__device__ float   g_v[B_ * KK];                    // current v

__global__ void zero_s() { g_s[blockIdx.x * 1024 + threadIdx.x] = 0.f; }

__device__ __forceinline__ unsigned long long pack2(float a, float b) {
    unsigned long long r;
    asm("mov.b64 %0, {%1, %2};" : "=l"(r) : "f"(a), "f"(b));
    return r;
}
__device__ __forceinline__ void fma2(unsigned long long& d,
                                     unsigned long long a, unsigned long long b) {
    asm("fma.rn.f32x2 %0, %1, %2, %0;" : "+l"(d) : "l"(a), "l"(b));
}

// ---------------------------------------------------------------------------
// Kernel 1: u[b,j,k] = sum_i x[b,j,i] * W[j,i,k] -> fp16.  One block per j.
// Thread owns 2 adjacent k packed in one f32x2 accumulator; 32 b accums.
// x pre-duplicated {x,x} in smem so inner loop = LDS.128 + FFMA2 only.
// ---------------------------------------------------------------------------
__global__ void __launch_bounds__(256) gemm_u(const float* __restrict__ x,
                                              const float* __restrict__ W) {
    const int j = blockIdx.x;
    const int t = threadIdx.x;
    __shared__ unsigned long long xsd[32][34];  // [b][i] = {x,x}; 16B-aligned rows
    {
        int lb = t >> 3, i0 = (t & 7) << 2;
        float4 xv = *(const float4*)(x + ((size_t)lb * NJ + j) * IL + i0);
        xsd[lb][i0 + 0] = pack2(xv.x, xv.x);
        xsd[lb][i0 + 1] = pack2(xv.y, xv.y);
        xsd[lb][i0 + 2] = pack2(xv.z, xv.z);
        xsd[lb][i0 + 3] = pack2(xv.w, xv.w);
    }
    __syncthreads();
    const float* Wj = W + (size_t)j * IL * KK;

    #pragma unroll 1
    for (int kk = 0; kk < 2; ++kk) {
        const int k = 2 * t + kk * 512;
        unsigned long long acc[32];
        #pragma unroll
        for (int b = 0; b < 32; ++b) acc[b] = 0ull;

        #pragma unroll 2
        for (int i4 = 0; i4 < 8; ++i4) {
            unsigned long long w0 = __ldg((const unsigned long long*)(Wj + (size_t)(i4 * 4 + 0) * KK + k));
            unsigned long long w1 = __ldg((const unsigned long long*)(Wj + (size_t)(i4 * 4 + 1) * KK + k));
            unsigned long long w2 = __ldg((const unsigned long long*)(Wj + (size_t)(i4 * 4 + 2) * KK + k));
            unsigned long long w3 = __ldg((const unsigned long long*)(Wj + (size_t)(i4 * 4 + 3) * KK + k));
            #pragma unroll
            for (int b = 0; b < 32; ++b) {
                ulonglong2 xa = *(const ulonglong2*)&xsd[b][i4 * 4];
                ulonglong2 xb = *(const ulonglong2*)&xsd[b][i4 * 4 + 2];
                fma2(acc[b], xa.x, w0);
                fma2(acc[b], xa.y, w1);
                fma2(acc[b], xb.x, w2);
                fma2(acc[b], xb.y, w3);
            }
        }
        #pragma unroll
        for (int b = 0; b < 32; ++b) {
            float2 f = *(const float2*)&acc[b];
            g_uh[(((size_t)b * NJ + j) * KK + k) >> 1] = __floats2half2_rn(f.x, f.y);
        }
    }
}

// ---------------------------------------------------------------------------
// Kernel 2: s0 = sum_j u / 32 + bias, v0 = squash(s0).  Block per (b,c).
// ---------------------------------------------------------------------------
__global__ void s0v0(const float* __restrict__ biases) {
    const int c = blockIdx.x, b = blockIdx.y, t = threadIdx.x;
    const int f4 = t & 3, jg = t >> 2;
    const float4* up = (const float4*)g_uh;

    float a[8];
    #pragma unroll
    for (int e = 0; e < 8; ++e) a[e] = 0.f;

    for (int j = jg; j < NJ; j += 64) {
        float4 r = up[((size_t)b * NJ + j) * (KK / 8) + c * 4 + f4];
        const __half2* h = (const __half2*)&r;
        #pragma unroll
        for (int p = 0; p < 4; ++p) {
            float2 f = __half22float2(h[p]);
            a[2 * p]     += f.x;
            a[2 * p + 1] += f.y;
        }
    }
    #pragma unroll
    for (int off = 16; off >= 4; off >>= 1)
        #pragma unroll
        for (int e = 0; e < 8; ++e)
            a[e] += __shfl_xor_sync(0xffffffffu, a[e], off);

    __shared__ float sred[8][4][8];
    int w = t >> 5, lane = t & 31;
    if (lane < 4) {
        #pragma unroll
        for (int e = 0; e < 8; ++e) sred[w][lane][e] = a[e];
    }
    __syncthreads();
    if (t < 4) {
        float p = 0.f;
        #pragma unroll
        for (int e = 0; e < 8; ++e) {
            float s = 0.f;
            #pragma unroll
            for (int w8 = 0; w8 < 8; ++w8) s += sred[w8][t][e];
            s = s * (1.0f / 32.0f) + biases[c * LL + t * 8 + e];
            a[e] = s;
            p += s * s;
        }
        p += __shfl_xor_sync(0xFu, p, 1);
        p += __shfl_xor_sync(0xFu, p, 2);
        float n = sqrtf(p);
        float coef = p / ((1.0f + p) * (n + 1e-7f));
        #pragma unroll
        for (int e = 0; e < 8; ++e)
            g_v[b * KK + c * LL + t * 8 + e] = coef * a[e];
    }
}

// ---------------------------------------------------------------------------
// Kernel 3: fused routing pass.  Warp owns 16 j rows, processed 2 at a time
// (8 LDG.128 in flight per iteration).
// Lane's float4 f(q) = q*32+lane covers halfs [8f, 8f+8):
//   c = q*8 + (lane>>2), in-c offset = (lane&3)*8.
// ---------------------------------------------------------------------------
__global__ void __launch_bounds__(256) route_pass(int read_b, int write_b) {
    const int b = blockIdx.y;
    const int t = threadIdx.x, w = t >> 5, lane = t & 31;
    const int g8 = lane >> 2, s4 = lane & 3;
    __shared__ float4 vs4[256];
    __shared__ float4 sred[4][256];
    vs4[t] = ((const float4*)g_v)[b * 256 + t];
    __syncthreads();

    float4 acc4[4][2];
    #pragma unroll
    for (int q = 0; q < 4; ++q) {
        acc4[q][0] = make_float4(0.f, 0.f, 0.f, 0.f);
        acc4[q][1] = make_float4(0.f, 0.f, 0.f, 0.f);
    }

    const int j0 = blockIdx.x * 128 + w * 16;
    for (int jj = 0; jj < 16; jj += 2) {
        const int j = j0 + jj;
        const float4* upA = (const float4*)g_uh + ((size_t)b * NJ + j) * (KK / 8);
        const float4* upB = upA + (KK / 8);

        float4 r[2][4];
        #pragma unroll
        for (int q = 0; q < 4; ++q) r[0][q] = __ldg(upA + q * 32 + lane);
        #pragma unroll
        for (int q = 0; q < 4; ++q) r[1][q] = __ldg(upB + q * 32 + lane);

        float dots[2][4];
        #pragma unroll
        for (int q = 0; q < 4; ++q) {
            float4 v0 = vs4[(q * 32 + lane) * 2];
            float4 v1 = vs4[(q * 32 + lane) * 2 + 1];
            #pragma unroll
            for (int p2 = 0; p2 < 2; ++p2) {
                const __half2* h = (const __half2*)&r[p2][q];
                float2 f0 = __half22float2(h[0]), f1 = __half22float2(h[1]);
                float2 f2 = __half22float2(h[2]), f3 = __half22float2(h[3]);
                float d = f0.x * v0.x + f0.y * v0.y + f1.x * v0.z + f1.y * v0.w
                        + f2.x * v1.x + f2.y * v1.y + f3.x * v1.z + f3.y * v1.w;
                d += __shfl_xor_sync(0xffffffffu, d, 1);
                d += __shfl_xor_sync(0xffffffffu, d, 2);
                dots[p2][q] = d;   // full dot for c = q*8+g8, replicated x4 lanes
            }
        }

        #pragma unroll
        for (int p2 = 0; p2 < 2; ++p2) {
            const size_t bbase = ((size_t)b * NJ + j + p2) * CC;
            if (read_b) {
                float bl = g_b[bbase + lane];
                #pragma unroll
                for (int q = 0; q < 4; ++q)
                    dots[p2][q] += __shfl_sync(0xffffffffu, bl, q * 8 + g8);
            }
            if (write_b) {
                float wv = dots[p2][0];
                if (s4 == 1) wv = dots[p2][1];
                if (s4 == 2) wv = dots[p2][2];
                if (s4 == 3) wv = dots[p2][3];
                g_b[bbase + s4 * 8 + g8] = wv;  // bijective lane -> c map
            }
        }

        // softmax over all 32 c (both j's interleaved)
        float m[2], se[2];
        #pragma unroll
        for (int p2 = 0; p2 < 2; ++p2) {
            m[p2] = fmaxf(fmaxf(dots[p2][0], dots[p2][1]),
                          fmaxf(dots[p2][2], dots[p2][3]));
            m[p2] = fmaxf(m[p2], __shfl_xor_sync(0xffffffffu, m[p2], 4));
            m[p2] = fmaxf(m[p2], __shfl_xor_sync(0xffffffffu, m[p2], 8));
            m[p2] = fmaxf(m[p2], __shfl_xor_sync(0xffffffffu, m[p2], 16));
        }
        #pragma unroll
        for (int p2 = 0; p2 < 2; ++p2) {
            se[p2] = 0.f;
            #pragma unroll
            for (int q = 0; q < 4; ++q) {
                dots[p2][q] = __expf(dots[p2][q] - m[p2]);
                se[p2] += dots[p2][q];
            }
            se[p2] += __shfl_xor_sync(0xffffffffu, se[p2], 4);
            se[p2] += __shfl_xor_sync(0xffffffffu, se[p2], 8);
            se[p2] += __shfl_xor_sync(0xffffffffu, se[p2], 16);
        }
        #pragma unroll
        for (int p2 = 0; p2 < 2; ++p2) {
            const float inv = 1.0f / se[p2];
            #pragma unroll
            for (int q = 0; q < 4; ++q) {
                float cp = dots[p2][q] * inv;
                const __half2* h = (const __half2*)&r[p2][q];
                float2 f0 = __half22float2(h[0]), f1 = __half22float2(h[1]);
                float2 f2 = __half22float2(h[2]), f3 = __half22float2(h[3]);
                acc4[q][0].x = fmaf(cp, f0.x, acc4[q][0].x);
                acc4[q][0].y = fmaf(cp, f0.y, acc4[q][0].y);
                acc4[q][0].z = fmaf(cp, f1.x, acc4[q][0].z);
                acc4[q][0].w = fmaf(cp, f1.y, acc4[q][0].w);
                acc4[q][1].x = fmaf(cp, f2.x, acc4[q][1].x);
                acc4[q][1].y = fmaf(cp, f2.y, acc4[q][1].y);
                acc4[q][1].z = fmaf(cp, f3.x, acc4[q][1].z);
                acc4[q][1].w = fmaf(cp, f3.y, acc4[q][1].w);
            }
        }
    }

    // tree reduce 8 -> 4 -> 2 -> 1 warps
    if (w >= 4) {
        #pragma unroll
        for (int q = 0; q < 4; ++q) {
            sred[w - 4][q * 64 + lane * 2]     = acc4[q][0];
            sred[w - 4][q * 64 + lane * 2 + 1] = acc4[q][1];
        }
    }
    __syncthreads();
    if (w < 4) {
        #pragma unroll
        for (int q = 0; q < 4; ++q) {
            float4 o0 = sred[w][q * 64 + lane * 2];
            float4 o1 = sred[w][q * 64 + lane * 2 + 1];
            acc4[q][0].x += o0.x; acc4[q][0].y += o0.y;
            acc4[q][0].z += o0.z; acc4[q][0].w += o0.w;
            acc4[q][1].x += o1.x; acc4[q][1].y += o1.y;
            acc4[q][1].z += o1.z; acc4[q][1].w += o1.w;
        }
    }
    __syncthreads();
    if (w >= 2 && w < 4) {
        #pragma unroll
        for (int q = 0; q < 4; ++q) {
            sred[w - 2][q * 64 + lane * 2]     = acc4[q][0];
            sred[w - 2][q * 64 + lane * 2 + 1] = acc4[q][1];
        }
    }
    __syncthreads();
    if (w < 2) {
        #pragma unroll
        for (int q = 0; q < 4; ++q) {
            float4 o0 = sred[w][q * 64 + lane * 2];
            float4 o1 = sred[w][q * 64 + lane * 2 + 1];
            acc4[q][0].x += o0.x; acc4[q][0].y += o0.y;
            acc4[q][0].z += o0.z; acc4[q][0].w += o0.w;
            acc4[q][1].x += o1.x; acc4[q][1].y += o1.y;
            acc4[q][1].z += o1.z; acc4[q][1].w += o1.w;
        }
    }
    __syncthreads();
    if (w == 1) {
        #pragma unroll
        for (int q = 0; q < 4; ++q) {
            sred[0][q * 64 + lane * 2]     = acc4[q][0];
            sred[0][q * 64 + lane * 2 + 1] = acc4[q][1];
        }
    }
    __syncthreads();
    if (w == 0) {
        #pragma unroll
        for (int q = 0; q < 4; ++q) {
            float4 o0 = sred[0][q * 64 + lane * 2];
            float4 o1 = sred[0][q * 64 + lane * 2 + 1];
            acc4[q][0].x += o0.x; acc4[q][0].y += o0.y;
            acc4[q][0].z += o0.z; acc4[q][0].w += o0.w;
            acc4[q][1].x += o1.x; acc4[q][1].y += o1.y;
            acc4[q][1].z += o1.z; acc4[q][1].w += o1.w;
            float* sp = g_s + b * KK + (q * 32 + lane) * 8;
            atomicAdd(sp + 0, acc4[q][0].x);
            atomicAdd(sp + 1, acc4[q][0].y);
            atomicAdd(sp + 2, acc4[q][0].z);
            atomicAdd(sp + 3, acc4[q][0].w);
            atomicAdd(sp + 4, acc4[q][1].x);
            atomicAdd(sp + 5, acc4[q][1].y);
            atomicAdd(sp + 6, acc4[q][1].z);
            atomicAdd(sp + 7, acc4[q][1].w);
        }
    }
}

// ---------------------------------------------------------------------------
// Kernel 4: v = squash(s + bias); re-zeroes g_s.  One warp per (b,c).
// ---------------------------------------------------------------------------
__global__ void finalize(const float* __restrict__ biases,
                         float* __restrict__ out, int write_out) {
    int t = threadIdx.x, w = t >> 5, lane = t & 31;
    int bc = blockIdx.x * 8 + w;
    int c = bc & 31;
    float s = g_s[bc * 32 + lane] + biases[c * 32 + lane];
    g_s[bc * 32 + lane] = 0.f;          // prep next accumulation
    float p = s * s;
    #pragma unroll
    for (int off = 16; off; off >>= 1)
        p += __shfl_xor_sync(0xffffffffu, p, off);
    float n = sqrtf(p);
    float coef = p / ((1.0f + p) * (n + 1e-7f));
    float v = coef * s;
    if (write_out) out[bc * 32 + lane] = v;
    else           g_v[bc * 32 + lane] = v;
}

// ---------------------------------------------------------------------------
extern "C" void kernel_launch(void* const* d_in, const int* in_sizes, int n_in,
                              void* d_out, int out_size) {
    const float* x      = (const float*)d_in[0];  // [B,NJ,IL]
    const float* W      = (const float*)d_in[1];  // [NJ, IL, KK]
    const float* biases = (const float*)d_in[2];  // [CC, LL]
    float* out = (float*)d_out;                   // [B, CC, LL]

    zero_s<<<32, 1024>>>();
    gemm_u<<<NJ, 256>>>(x, W);                    // u (fp16), FFMA2 inner loop
    s0v0<<<dim3(CC, B_), 256>>>(biases);          // r=0: v0

    route_pass<<<dim3(16, B_), 256>>>(0, 1);      // b1 = dot(u,v0); c1; s1
    finalize<<<128, 256>>>(biases, out, 0);       // v1 (zeroes g_s)

    route_pass<<<dim3(16, B_), 256>>>(1, 0);      // b2 = b1 + dot(u,v1); c2; s2
    finalize<<<128, 256>>>(biases, out, 1);       // v2 -> output
}